// round 17
// baseline (speedup 1.0000x reference)
#include <cuda_runtime.h>

// C4ByteTransformer R16: circular-conv (R15) + 2-way CTA split per step.
// grid=8: CTA (step = bx>>1, half = bx&1) computes outputs d in
// [128*half, 128*half+128) of its step. Z[m] = circular conv of EA,EB:
//   num[d] = E0*Z[d] + E1*Z[(d-1)&255].
// Each CTA computes its 128 Z values (32 MACs/thread) + the boundary
// Z[m_base-1] (warp 31, 256-MAC dot). Carry-chain triples {Tlow,S255,Sums}
// from O(256) prefix-scan closed forms, redundant per CTA (R12-validated).
// Zero inter-CTA communication; classic launch.

__global__ __launch_bounds__(1024, 1)
void c4_split_kernel(const float* __restrict__ a_emb,
                     const float* __restrict__ b_emb,
                     float* __restrict__ out) {
    __shared__ __align__(16) float EA_all[1024];   // [s][a], all 4 steps
    __shared__ __align__(16) float EBc2[512];      // own-step EB duplicated x2
    __shared__ __align__(16) float Spart[32 * 128];
    __shared__ __align__(16) float Zsh[132];       // [0]=Z[mb-1], [1+i]=Z[mb+i]
    __shared__ float chunkTot[32];                 // per-warp chunk sums of EB
    __shared__ float Trip[4][4];                   // [s]{Tlow, S255, SumA, SumB}

    const int tid    = threadIdx.x;
    const int step   = blockIdx.x >> 1;
    const int m_base = (blockIdx.x & 1) << 7;      // 0 or 128
    const int lane   = tid & 31;
    const int w      = tid >> 5;                   // warp 0..31

    // ---- Phase A: all 4 steps' exponentials; thread=(s=tid>>8, e=tid&255) ----
    const float av  = a_emb[tid];
    const float bv  = b_emb[tid];
    const float eav = __expf(10.f * av);
    const float ebv = __expf(10.f * bv);
    EA_all[tid] = eav;
    if ((tid >> 8) == step) {                      // own-step EB, duplicated
        const int e = tid & 255;
        EBc2[e]       = ebv;
        EBc2[256 + e] = ebv;
    }
    if (tid < 16) ((float*)Trip)[tid] = 0.f;
    __syncthreads();                               // #1

    const float* EA = &EA_all[step << 8];

    // ---- Phase B: circular conv partials. warp=a-slice(8), lane=m-group(4) ----
    // Z[m] = sum_a EA[a]*EBc2[256+m-a];  w[i] = EBc2[J0-4k+i], s_r uses w[4+r-da]
    {
        const int abase = w << 3;
        const int m0    = m_base + (lane << 2);
        const int J0    = 252 + m0 - abase;        // in [4, 504], 16B aligned
        float4 lo = *(const float4*)&EBc2[J0];
        float4 hi = *(const float4*)&EBc2[J0 + 4];
        float s0 = 0.f, s1 = 0.f, s2 = 0.f, s3 = 0.f;
        #pragma unroll
        for (int k = 0; k < 2; ++k) {
            float4 ea = *(const float4*)&EA[abase + 4 * k];
            s0 = fmaf(ea.x, hi.x, s0); s1 = fmaf(ea.x, hi.y, s1);
            s2 = fmaf(ea.x, hi.z, s2); s3 = fmaf(ea.x, hi.w, s3);
            s0 = fmaf(ea.y, lo.w, s0); s1 = fmaf(ea.y, hi.x, s1);
            s2 = fmaf(ea.y, hi.y, s2); s3 = fmaf(ea.y, hi.z, s3);
            s0 = fmaf(ea.z, lo.z, s0); s1 = fmaf(ea.z, lo.w, s1);
            s2 = fmaf(ea.z, hi.x, s2); s3 = fmaf(ea.z, hi.y, s3);
            s0 = fmaf(ea.w, lo.y, s0); s1 = fmaf(ea.w, lo.z, s1);
            s2 = fmaf(ea.w, lo.w, s2); s3 = fmaf(ea.w, hi.x, s3);
            if (k < 1) { hi = lo; lo = *(const float4*)&EBc2[J0 - 4]; }
        }
        *(float4*)&Spart[(w << 7) + (lane << 2)] = make_float4(s0, s1, s2, s3);
    }

    // ---- boundary Z[(m_base-1) & 255]: warp 31, 256-MAC dot + reduce ----
    if (w == 31) {
        const int jb = 256 + m_base - 1;           // j = jb - a, in [0, 383]
        float zb = 0.f;
        #pragma unroll
        for (int t = 0; t < 8; ++t) {
            const int a = lane + (t << 5);
            zb = fmaf(EA[a], EBc2[jb - a], zb);
        }
        #pragma unroll
        for (int off = 16; off > 0; off >>= 1)
            zb += __shfl_down_sync(0xffffffffu, zb, off);
        if (lane == 0) Zsh[0] = zb;
    }

    // ---- Phase S1: warp inclusive scan of EB (thread=(s,j)) ----
    float pb = ebv;
    #pragma unroll
    for (int off = 1; off < 32; off <<= 1) {
        float n = __shfl_up_sync(0xffffffffu, pb, off);
        if (lane >= off) pb += n;
    }
    if (lane == 31) chunkTot[w] = pb;
    __syncthreads();                               // #2 (Spart+Zsh[0]+chunkTot)

    // ---- Phase S2: finish prefix, triple contributions, reduce ----
    {
        const int c = w & 7, sbase = (w >> 3) << 3;
        float offsum = 0.f;
        for (int cc = 0; cc < c; ++cc) offsum += chunkTot[sbase + cc];
        pb += offsum;                              // inclusive prefix PB[j]
    }
    {
        const int sj = tid >> 8, j = tid & 255;
        const float ea_rev = EA_all[(sj << 8) + 255 - j];
        float cl = ea_rev * pb;                    // -> Tlow
        float cs = ea_rev * ebv;                   // -> S255
        float ca = eav;                            // -> SumA
        float cb = ebv;                            // -> SumB
        #pragma unroll
        for (int off = 16; off > 0; off >>= 1) {
            cl += __shfl_down_sync(0xffffffffu, cl, off);
            cs += __shfl_down_sync(0xffffffffu, cs, off);
            ca += __shfl_down_sync(0xffffffffu, ca, off);
            cb += __shfl_down_sync(0xffffffffu, cb, off);
        }
        if (lane == 0) {
            atomicAdd(&Trip[sj][0], cl);
            atomicAdd(&Trip[sj][1], cs);
            atomicAdd(&Trip[sj][2], ca);
            atomicAdd(&Trip[sj][3], cb);
        }
    }

    // ---- Phase C: combine conv partials into Zsh[1..128] ----
    if (tid < 128) {
        float s = 0.f;
        #pragma unroll
        for (int p = 0; p < 32; ++p) s += Spart[(p << 7) + tid];
        Zsh[1 + tid] = s;                          // Z[m_base + tid]
    }
    __syncthreads();                               // #3 (Trip atomics + Zsh)

    // ---- Phase F: per-thread carry chain + outputs (tid<128) ----
    if (tid < 128) {
        float E0s = 1.f, E1s = 1.f, iZs = 1.f;
        float c0 = 1.f, c1 = 0.f;                  // carry0 = (1, 0)
        #pragma unroll
        for (int s = 0; s < 4; ++s) {
            const float Tlow  = Trip[s][0];
            const float S255  = Trip[s][1];
            const float Tall  = Trip[s][2] * Trip[s][3];
            const float Thigh = Tall - Tlow;
            const float E0 = __expf(10.f * c0), E1 = __expf(10.f * c1);
            const float iZ = 1.0f / ((E0 + E1) * Tall);
            if (s == step) { E0s = E0; E1s = E1; iZs = iZ; }
            c0 = (E0 * Tlow  + E1 * (Tlow  - S255)) * iZ;
            c1 = (E0 * Thigh + E1 * (Thigh + S255)) * iZ;
        }
        // d = m_base + tid:  num = E0*Z[d] + E1*Z[(d-1)&255]
        const float num = E0s * Zsh[1 + tid] + E1s * Zsh[tid];
        out[(step << 8) + m_base + tid] = num * iZs;
    }
}

extern "C" void kernel_launch(void* const* d_in, const int* in_sizes, int n_in,
                              void* d_out, int out_size) {
    const float* a_emb = (const float*)d_in[0];   // [4, 256]
    const float* b_emb = (const float*)d_in[1];   // [4, 256]
    float* out = (float*)d_out;                   // [4, 256]
    (void)in_sizes; (void)n_in; (void)out_size;
    c4_split_kernel<<<8, 1024>>>(a_emb, b_emb, out);
}